// round 4
// baseline (speedup 1.0000x reference)
#include <cuda_runtime.h>
#include <cuda_bf16.h>
#include <cstdint>

// Problem constants
#define BB 32
#define NN 1024
#define FIN 512
#define H1 256
#define H2 128

// ---------------- scratch (static device globals; no allocations allowed) ---
__device__ float g_h1[(size_t)BB * NN * H1];   // 33.5 MB
__device__ float g_g1[(size_t)BB * NN * H1];   // 33.5 MB
__device__ float g_h2[(size_t)BB * NN * H2];   // 16.8 MB
__device__ float g_el1[BB * NN], g_er1[BB * NN];
__device__ float g_el2[BB * NN], g_er2[BB * NN];
__device__ float g_st1[2 * BB], g_st2[2 * BB];
__device__ float g_v[BB * NN];

// ---------------- generic tiled GEMM: C[M,NC] = A[M,K] @ W[K,NC] ------------
// BM=64, BN=64, BK=16, 256 threads, 4x4 per-thread tile.
template<int K, int NC>
__global__ __launch_bounds__(256) void gemm_kernel(
    const float* __restrict__ A, const float* __restrict__ W, float* __restrict__ C)
{
    __shared__ float As[16][65];   // [k][m], padded
    __shared__ float Bs[16][64];   // [k][n]
    const int tid = threadIdx.x;
    const int m0 = blockIdx.x * 64, n0 = blockIdx.y * 64;
    const int ty = tid >> 4, tx = tid & 15;
    const int arow = tid >> 2, acol = (tid & 3) * 4;
    const int brow = tid >> 4, bcol = (tid & 15) * 4;
    const float* Ap = A + (size_t)(m0 + arow) * K + acol;

    float acc[4][4] = {};
    for (int k0 = 0; k0 < K; k0 += 16) {
        float4 av = *reinterpret_cast<const float4*>(Ap + k0);
        As[acol + 0][arow] = av.x; As[acol + 1][arow] = av.y;
        As[acol + 2][arow] = av.z; As[acol + 3][arow] = av.w;
        float4 wv = *reinterpret_cast<const float4*>(
            W + (size_t)(k0 + brow) * NC + n0 + bcol);
        *reinterpret_cast<float4*>(&Bs[brow][bcol]) = wv;
        __syncthreads();
        #pragma unroll
        for (int k = 0; k < 16; k++) {
            float a[4];
            #pragma unroll
            for (int i = 0; i < 4; i++) a[i] = As[k][ty * 4 + i];
            float4 bv = *reinterpret_cast<const float4*>(&Bs[k][tx * 4]);
            float bb[4] = {bv.x, bv.y, bv.z, bv.w};
            #pragma unroll
            for (int i = 0; i < 4; i++)
                #pragma unroll
                for (int j = 0; j < 4; j++)
                    acc[i][j] = fmaf(a[i], bb[j], acc[i][j]);
        }
        __syncthreads();
    }
    #pragma unroll
    for (int i = 0; i < 4; i++) {
        float4 o = {acc[i][0], acc[i][1], acc[i][2], acc[i][3]};
        *reinterpret_cast<float4*>(&C[(size_t)(m0 + ty * 4 + i) * NC + n0 + tx * 4]) = o;
    }
}

// ---------------- el/er projections: el[r] = h[r,:].a[0:FO], er uses a[FO:] -
template<int FO>
__global__ __launch_bounds__(256) void eler_kernel(
    const float* __restrict__ H, const float* __restrict__ a,
    float* __restrict__ el, float* __restrict__ er)
{
    int row = (blockIdx.x * 256 + threadIdx.x) >> 5;
    int lane = threadIdx.x & 31;
    const float* h = H + (size_t)row * FO;
    float se = 0.f, sr = 0.f;
    #pragma unroll
    for (int f = lane * 4; f < FO; f += 128) {
        float4 hv = *reinterpret_cast<const float4*>(h + f);
        float4 al = *reinterpret_cast<const float4*>(a + f);
        float4 ar = *reinterpret_cast<const float4*>(a + FO + f);
        se += hv.x * al.x + hv.y * al.y + hv.z * al.z + hv.w * al.w;
        sr += hv.x * ar.x + hv.y * ar.y + hv.z * ar.z + hv.w * ar.w;
    }
    #pragma unroll
    for (int o = 16; o; o >>= 1) {
        se += __shfl_xor_sync(0xffffffffu, se, o);
        sr += __shfl_xor_sync(0xffffffffu, sr, o);
    }
    if (lane == 0) { el[row] = se; er[row] = sr; }
}

// ---------------- per-batch min/max -> affine coefficients ------------------
// att(i,j) = sigmoid(leaky(el_i+er_j)*c1 + c0); c1=30/(mx-mn), c0=-mn*c1-20
__global__ __launch_bounds__(256) void stat_kernel(
    const float* __restrict__ el, const float* __restrict__ er, float* __restrict__ st)
{
    int b = blockIdx.x, tid = threadIdx.x;
    const float* e1 = el + b * NN;
    const float* e2 = er + b * NN;
    float mnl = 1e30f, mxl = -1e30f, mnr = 1e30f, mxr = -1e30f;
    for (int i = tid; i < NN; i += 256) {
        float v = e1[i]; mnl = fminf(mnl, v); mxl = fmaxf(mxl, v);
        float w = e2[i]; mnr = fminf(mnr, w); mxr = fmaxf(mxr, w);
    }
    #pragma unroll
    for (int o = 16; o; o >>= 1) {
        mnl = fminf(mnl, __shfl_xor_sync(0xffffffffu, mnl, o));
        mxl = fmaxf(mxl, __shfl_xor_sync(0xffffffffu, mxl, o));
        mnr = fminf(mnr, __shfl_xor_sync(0xffffffffu, mnr, o));
        mxr = fmaxf(mxr, __shfl_xor_sync(0xffffffffu, mxr, o));
    }
    __shared__ float sm[4][8];
    int wid = tid >> 5, lane = tid & 31;
    if (lane == 0) { sm[0][wid] = mnl; sm[1][wid] = mxl; sm[2][wid] = mnr; sm[3][wid] = mxr; }
    __syncthreads();
    if (tid == 0) {
        for (int w = 1; w < 8; w++) {
            mnl = fminf(mnl, sm[0][w]); mxl = fmaxf(mxl, sm[1][w]);
            mnr = fminf(mnr, sm[2][w]); mxr = fmaxf(mxr, sm[3][w]);
        }
        float s = mnl + mnr, t = mxl + mxr;
        float mn = s > 0.f ? s : 0.01f * s;
        float mx = t > 0.f ? t : 0.01f * t;
        float c1 = 30.f / (mx - mn);
        st[2 * b] = c1;
        st[2 * b + 1] = -mn * c1 - 20.f;
    }
}

// ---------------- attention GEMM: G = [ELU]( att @ H ), att on-the-fly ------
// Per batch (grid.z). BM=64 rows, BN=128 cols, BK=32. 256 threads, 4x8 tile.
// Optionally writes the att tile to attOut (layer 2: fc2 is an output).
template<int FOUT, bool WRITE_ATT, bool DO_ELU>
__global__ __launch_bounds__(256) void attn_kernel(
    const float* __restrict__ el, const float* __restrict__ er,
    const float* __restrict__ st, const float* __restrict__ H,
    float* __restrict__ G, float* __restrict__ attOut)
{
    __shared__ float As[32][65];    // [k][m] att tile, padded
    __shared__ float Bs[32][128];   // [k][n] H tile
    const int b = blockIdx.z;
    const int i0 = blockIdx.x * 64;
    const int n0 = blockIdx.y * 128;
    const int tid = threadIdx.x;
    const int ty = tid >> 4, tx = tid & 15;
    const int am = tid >> 2, ak = (tid & 3) * 8;
    const float c1 = st[2 * b], c0 = st[2 * b + 1];
    const float* erb = er + b * NN;
    const float el_m = el[b * NN + i0 + am];
    const float* Hb = H + (size_t)b * NN * FOUT;
    const int lr = tid >> 5, lc = (tid & 31) * 4;

    float acc[4][8] = {};
    for (int k0 = 0; k0 < NN; k0 += 32) {
        // stage H tile
        #pragma unroll
        for (int it = 0; it < 4; it++) {
            int r = lr + it * 8;
            *reinterpret_cast<float4*>(&Bs[r][lc]) =
                *reinterpret_cast<const float4*>(&Hb[(size_t)(k0 + r) * FOUT + n0 + lc]);
        }
        // compute att tile (8 values per thread)
        float attv[8];
        #pragma unroll
        for (int q = 0; q < 8; q++) {
            float s = el_m + erb[k0 + ak + q];
            float l = s > 0.f ? s : 0.01f * s;
            float t = fmaf(l, c1, c0);
            float a = 1.f / (1.f + __expf(-t));
            attv[q] = a;
            As[ak + q][am] = a;
        }
        if constexpr (WRITE_ATT) {
            size_t base = ((size_t)b * NN + i0 + am) * NN + k0 + ak;
            float4 p0 = {attv[0], attv[1], attv[2], attv[3]};
            float4 p1 = {attv[4], attv[5], attv[6], attv[7]};
            *reinterpret_cast<float4*>(&attOut[base]) = p0;
            *reinterpret_cast<float4*>(&attOut[base + 4]) = p1;
        }
        __syncthreads();
        #pragma unroll
        for (int k = 0; k < 32; k++) {
            float a[4];
            #pragma unroll
            for (int i = 0; i < 4; i++) a[i] = As[k][ty * 4 + i];
            float4 b0 = *reinterpret_cast<const float4*>(&Bs[k][tx * 8]);
            float4 b1 = *reinterpret_cast<const float4*>(&Bs[k][tx * 8 + 4]);
            float bb[8] = {b0.x, b0.y, b0.z, b0.w, b1.x, b1.y, b1.z, b1.w};
            #pragma unroll
            for (int i = 0; i < 4; i++)
                #pragma unroll
                for (int j = 0; j < 8; j++)
                    acc[i][j] = fmaf(a[i], bb[j], acc[i][j]);
        }
        __syncthreads();
    }
    #pragma unroll
    for (int i = 0; i < 4; i++) {
        float o[8];
        #pragma unroll
        for (int j = 0; j < 8; j++) {
            float v = acc[i][j];
            if constexpr (DO_ELU) v = v > 0.f ? v : (__expf(v) - 1.f);
            o[j] = v;
        }
        float* dst = &G[(size_t)(b * NN + i0 + ty * 4 + i) * FOUT + n0 + tx * 8];
        float4 q0 = {o[0], o[1], o[2], o[3]}, q1 = {o[4], o[5], o[6], o[7]};
        *reinterpret_cast<float4*>(dst) = q0;
        *reinterpret_cast<float4*>(dst + 4) = q1;
    }
}

// ---------------- v[r] = g2[r,:] . Wg  (H2=128) -----------------------------
__global__ __launch_bounds__(256) void v_kernel(
    const float* __restrict__ g2, const float* __restrict__ Wg, float* __restrict__ v)
{
    int row = (blockIdx.x * 256 + threadIdx.x) >> 5;
    int lane = threadIdx.x & 31;
    const float* g = g2 + (size_t)row * H2;
    float4 gv = *reinterpret_cast<const float4*>(&g[lane * 4]);
    float4 wv = *reinterpret_cast<const float4*>(&Wg[lane * 4]);
    float s = gv.x * wv.x + gv.y * wv.y + gv.z * wv.z + gv.w * wv.w;
    #pragma unroll
    for (int o = 16; o; o >>= 1) s += __shfl_xor_sync(0xffffffffu, s, o);
    if (lane == 0) v[row] = s;
}

// ---------------- out[b,i] = leaky( fc2[b,i,:] . v[b,:] + bg ) --------------
__global__ __launch_bounds__(256) void z_kernel(
    const float* __restrict__ fc2, const float* __restrict__ v,
    const float* __restrict__ bg, float* __restrict__ out)
{
    __shared__ float vs[NN];
    int b = blockIdx.x >> 7;                       // 128 blocks per batch
    int rloc = (blockIdx.x & 127) * 8 + (threadIdx.x >> 5);
    int lane = threadIdx.x & 31;
    *reinterpret_cast<float4*>(&vs[threadIdx.x * 4]) =
        *reinterpret_cast<const float4*>(&v[b * NN + threadIdx.x * 4]);
    __syncthreads();
    size_t row = (size_t)b * NN + rloc;
    const float* f = fc2 + row * NN;
    float s = 0.f;
    for (int j = lane * 4; j < NN; j += 128) {
        float4 a = *reinterpret_cast<const float4*>(f + j);
        s += a.x * vs[j] + a.y * vs[j + 1] + a.z * vs[j + 2] + a.w * vs[j + 3];
    }
    #pragma unroll
    for (int o = 16; o; o >>= 1) s += __shfl_xor_sync(0xffffffffu, s, o);
    if (lane == 0) {
        float zz = s + bg[0];
        out[row] = zz > 0.f ? zz : 0.01f * zz;
    }
}

// ---------------- launch ----------------------------------------------------
extern "C" void kernel_launch(void* const* d_in, const int* in_sizes, int n_in,
                              void* d_out, int out_size)
{
    const float* x  = (const float*)d_in[0];
    // d_in[1] = edge_weight (unused by the reference)
    const float* W1 = (const float*)d_in[2];
    const float* a1 = (const float*)d_in[3];
    const float* W2 = (const float*)d_in[4];
    const float* a2 = (const float*)d_in[5];
    const float* Wg = (const float*)d_in[6];
    const float* bg = (const float*)d_in[7];

    float* out = (float*)d_out;                                 // [B,N,1]
    float* fc2 = out + (size_t)BB * NN;                         // [B,N,N]
    float* g2  = fc2 + (size_t)BB * NN * NN;                    // [B,N,H2]

    float *h1, *g1, *h2, *el1, *er1, *el2, *er2, *st1, *st2, *vv;
    cudaGetSymbolAddress((void**)&h1,  g_h1);
    cudaGetSymbolAddress((void**)&g1,  g_g1);
    cudaGetSymbolAddress((void**)&h2,  g_h2);
    cudaGetSymbolAddress((void**)&el1, g_el1);
    cudaGetSymbolAddress((void**)&er1, g_er1);
    cudaGetSymbolAddress((void**)&el2, g_el2);
    cudaGetSymbolAddress((void**)&er2, g_er2);
    cudaGetSymbolAddress((void**)&st1, g_st1);
    cudaGetSymbolAddress((void**)&st2, g_st2);
    cudaGetSymbolAddress((void**)&vv,  g_v);

    // Layer 1
    gemm_kernel<FIN, H1><<<dim3(BB * NN / 64, H1 / 64), 256>>>(x, W1, h1);
    eler_kernel<H1><<<BB * NN / 8, 256>>>(h1, a1, el1, er1);
    stat_kernel<<<BB, 256>>>(el1, er1, st1);
    attn_kernel<H1, false, true><<<dim3(NN / 64, H1 / 128, BB), 256>>>(
        el1, er1, st1, h1, g1, nullptr);

    // Layer 2
    gemm_kernel<H1, H2><<<dim3(BB * NN / 64, H2 / 64), 256>>>(g1, W2, h2);
    eler_kernel<H2><<<BB * NN / 8, 256>>>(h2, a2, el2, er2);
    stat_kernel<<<BB, 256>>>(el2, er2, st2);
    attn_kernel<H2, true, false><<<dim3(NN / 64, H2 / 128, BB), 256>>>(
        el2, er2, st2, h2, g2, fc2);

    // Readout: z = fc2 @ (g2 @ Wg) + bg ; out = leaky(z)
    v_kernel<<<BB * NN / 8, 256>>>(g2, Wg, vv);
    z_kernel<<<BB * NN / 8, 256>>>(fc2, vv, bg, out);
}

// round 5
// speedup vs baseline: 1.0018x; 1.0018x over previous
#include <cuda_runtime.h>
#include <cuda_bf16.h>
#include <cstdint>

// Problem constants
#define BB 32
#define NN 1024
#define FIN 512
#define H1 256
#define H2 128

// ---------------- scratch (static device globals; no allocations allowed) ---
__device__ float g_h1[(size_t)BB * NN * H1];   // 33.5 MB
__device__ float g_g1[(size_t)BB * NN * H1];   // 33.5 MB
__device__ float g_h2[(size_t)BB * NN * H2];   // 16.8 MB
__device__ float g_el1[BB * NN], g_er1[BB * NN];
__device__ float g_el2[BB * NN], g_er2[BB * NN];
__device__ float g_st1[2 * BB], g_st2[2 * BB];
__device__ float g_v[BB * NN];

// ---------------- generic tiled GEMM: C[M,NC] = A[M,K] @ W[K,NC] ------------
// BM=64, BN=64, BK=16, 256 threads, 4x4 per-thread tile.
template<int K, int NC>
__global__ __launch_bounds__(256) void gemm_kernel(
    const float* __restrict__ A, const float* __restrict__ W, float* __restrict__ C)
{
    __shared__ float As[16][65];   // [k][m], padded
    __shared__ float Bs[16][64];   // [k][n]
    const int tid = threadIdx.x;
    const int m0 = blockIdx.x * 64, n0 = blockIdx.y * 64;
    const int ty = tid >> 4, tx = tid & 15;
    const int arow = tid >> 2, acol = (tid & 3) * 4;
    const int brow = tid >> 4, bcol = (tid & 15) * 4;
    const float* Ap = A + (size_t)(m0 + arow) * K + acol;

    float acc[4][4] = {};
    for (int k0 = 0; k0 < K; k0 += 16) {
        float4 av = *reinterpret_cast<const float4*>(Ap + k0);
        As[acol + 0][arow] = av.x; As[acol + 1][arow] = av.y;
        As[acol + 2][arow] = av.z; As[acol + 3][arow] = av.w;
        float4 wv = *reinterpret_cast<const float4*>(
            W + (size_t)(k0 + brow) * NC + n0 + bcol);
        *reinterpret_cast<float4*>(&Bs[brow][bcol]) = wv;
        __syncthreads();
        #pragma unroll
        for (int k = 0; k < 16; k++) {
            float a[4];
            #pragma unroll
            for (int i = 0; i < 4; i++) a[i] = As[k][ty * 4 + i];
            float4 bv = *reinterpret_cast<const float4*>(&Bs[k][tx * 4]);
            float bb[4] = {bv.x, bv.y, bv.z, bv.w};
            #pragma unroll
            for (int i = 0; i < 4; i++)
                #pragma unroll
                for (int j = 0; j < 4; j++)
                    acc[i][j] = fmaf(a[i], bb[j], acc[i][j]);
        }
        __syncthreads();
    }
    #pragma unroll
    for (int i = 0; i < 4; i++) {
        float4 o = {acc[i][0], acc[i][1], acc[i][2], acc[i][3]};
        *reinterpret_cast<float4*>(&C[(size_t)(m0 + ty * 4 + i) * NC + n0 + tx * 4]) = o;
    }
}

// ---------------- el/er projections: el[r] = h[r,:].a[0:FO], er uses a[FO:] -
template<int FO>
__global__ __launch_bounds__(256) void eler_kernel(
    const float* __restrict__ H, const float* __restrict__ a,
    float* __restrict__ el, float* __restrict__ er)
{
    int row = (blockIdx.x * 256 + threadIdx.x) >> 5;
    int lane = threadIdx.x & 31;
    const float* h = H + (size_t)row * FO;
    float se = 0.f, sr = 0.f;
    #pragma unroll
    for (int f = lane * 4; f < FO; f += 128) {
        float4 hv = *reinterpret_cast<const float4*>(h + f);
        float4 al = *reinterpret_cast<const float4*>(a + f);
        float4 ar = *reinterpret_cast<const float4*>(a + FO + f);
        se += hv.x * al.x + hv.y * al.y + hv.z * al.z + hv.w * al.w;
        sr += hv.x * ar.x + hv.y * ar.y + hv.z * ar.z + hv.w * ar.w;
    }
    #pragma unroll
    for (int o = 16; o; o >>= 1) {
        se += __shfl_xor_sync(0xffffffffu, se, o);
        sr += __shfl_xor_sync(0xffffffffu, sr, o);
    }
    if (lane == 0) { el[row] = se; er[row] = sr; }
}

// ---------------- per-batch min/max -> affine coefficients ------------------
// att(i,j) = sigmoid(leaky(el_i+er_j)*c1 + c0); c1=30/(mx-mn), c0=-mn*c1-20
__global__ __launch_bounds__(256) void stat_kernel(
    const float* __restrict__ el, const float* __restrict__ er, float* __restrict__ st)
{
    int b = blockIdx.x, tid = threadIdx.x;
    const float* e1 = el + b * NN;
    const float* e2 = er + b * NN;
    float mnl = 1e30f, mxl = -1e30f, mnr = 1e30f, mxr = -1e30f;
    for (int i = tid; i < NN; i += 256) {
        float v = e1[i]; mnl = fminf(mnl, v); mxl = fmaxf(mxl, v);
        float w = e2[i]; mnr = fminf(mnr, w); mxr = fmaxf(mxr, w);
    }
    #pragma unroll
    for (int o = 16; o; o >>= 1) {
        mnl = fminf(mnl, __shfl_xor_sync(0xffffffffu, mnl, o));
        mxl = fmaxf(mxl, __shfl_xor_sync(0xffffffffu, mxl, o));
        mnr = fminf(mnr, __shfl_xor_sync(0xffffffffu, mnr, o));
        mxr = fmaxf(mxr, __shfl_xor_sync(0xffffffffu, mxr, o));
    }
    __shared__ float sm[4][8];
    int wid = tid >> 5, lane = tid & 31;
    if (lane == 0) { sm[0][wid] = mnl; sm[1][wid] = mxl; sm[2][wid] = mnr; sm[3][wid] = mxr; }
    __syncthreads();
    if (tid == 0) {
        for (int w = 1; w < 8; w++) {
            mnl = fminf(mnl, sm[0][w]); mxl = fmaxf(mxl, sm[1][w]);
            mnr = fminf(mnr, sm[2][w]); mxr = fmaxf(mxr, sm[3][w]);
        }
        float s = mnl + mnr, t = mxl + mxr;
        float mn = s > 0.f ? s : 0.01f * s;
        float mx = t > 0.f ? t : 0.01f * t;
        float c1 = 30.f / (mx - mn);
        st[2 * b] = c1;
        st[2 * b + 1] = -mn * c1 - 20.f;
    }
}

// ---------------- attention GEMM: G = [ELU]( att @ H ), att on-the-fly ------
// Per batch (grid.z). BM=64 rows, BN=128 cols, BK=32. 256 threads, 4x8 tile.
// Optionally writes the att tile to attOut (layer 2: fc2 is an output).
template<int FOUT, bool WRITE_ATT, bool DO_ELU>
__global__ __launch_bounds__(256) void attn_kernel(
    const float* __restrict__ el, const float* __restrict__ er,
    const float* __restrict__ st, const float* __restrict__ H,
    float* __restrict__ G, float* __restrict__ attOut)
{
    __shared__ float As[32][65];    // [k][m] att tile, padded
    __shared__ float Bs[32][128];   // [k][n] H tile
    const int b = blockIdx.z;
    const int i0 = blockIdx.x * 64;
    const int n0 = blockIdx.y * 128;
    const int tid = threadIdx.x;
    const int ty = tid >> 4, tx = tid & 15;
    const int am = tid >> 2, ak = (tid & 3) * 8;
    const float c1 = st[2 * b], c0 = st[2 * b + 1];
    const float* erb = er + b * NN;
    const float el_m = el[b * NN + i0 + am];
    const float* Hb = H + (size_t)b * NN * FOUT;
    const int lr = tid >> 5, lc = (tid & 31) * 4;

    float acc[4][8] = {};
    for (int k0 = 0; k0 < NN; k0 += 32) {
        // stage H tile
        #pragma unroll
        for (int it = 0; it < 4; it++) {
            int r = lr + it * 8;
            *reinterpret_cast<float4*>(&Bs[r][lc]) =
                *reinterpret_cast<const float4*>(&Hb[(size_t)(k0 + r) * FOUT + n0 + lc]);
        }
        // compute att tile (8 values per thread)
        float attv[8];
        #pragma unroll
        for (int q = 0; q < 8; q++) {
            float s = el_m + erb[k0 + ak + q];
            float l = s > 0.f ? s : 0.01f * s;
            float t = fmaf(l, c1, c0);
            float a = 1.f / (1.f + __expf(-t));
            attv[q] = a;
            As[ak + q][am] = a;
        }
        if constexpr (WRITE_ATT) {
            size_t base = ((size_t)b * NN + i0 + am) * NN + k0 + ak;
            float4 p0 = {attv[0], attv[1], attv[2], attv[3]};
            float4 p1 = {attv[4], attv[5], attv[6], attv[7]};
            *reinterpret_cast<float4*>(&attOut[base]) = p0;
            *reinterpret_cast<float4*>(&attOut[base + 4]) = p1;
        }
        __syncthreads();
        #pragma unroll
        for (int k = 0; k < 32; k++) {
            float a[4];
            #pragma unroll
            for (int i = 0; i < 4; i++) a[i] = As[k][ty * 4 + i];
            float4 b0 = *reinterpret_cast<const float4*>(&Bs[k][tx * 8]);
            float4 b1 = *reinterpret_cast<const float4*>(&Bs[k][tx * 8 + 4]);
            float bb[8] = {b0.x, b0.y, b0.z, b0.w, b1.x, b1.y, b1.z, b1.w};
            #pragma unroll
            for (int i = 0; i < 4; i++)
                #pragma unroll
                for (int j = 0; j < 8; j++)
                    acc[i][j] = fmaf(a[i], bb[j], acc[i][j]);
        }
        __syncthreads();
    }
    #pragma unroll
    for (int i = 0; i < 4; i++) {
        float o[8];
        #pragma unroll
        for (int j = 0; j < 8; j++) {
            float v = acc[i][j];
            if constexpr (DO_ELU) v = v > 0.f ? v : (__expf(v) - 1.f);
            o[j] = v;
        }
        float* dst = &G[(size_t)(b * NN + i0 + ty * 4 + i) * FOUT + n0 + tx * 8];
        float4 q0 = {o[0], o[1], o[2], o[3]}, q1 = {o[4], o[5], o[6], o[7]};
        *reinterpret_cast<float4*>(dst) = q0;
        *reinterpret_cast<float4*>(dst + 4) = q1;
    }
}

// ---------------- v[r] = g2[r,:] . Wg  (H2=128) -----------------------------
__global__ __launch_bounds__(256) void v_kernel(
    const float* __restrict__ g2, const float* __restrict__ Wg, float* __restrict__ v)
{
    int row = (blockIdx.x * 256 + threadIdx.x) >> 5;
    int lane = threadIdx.x & 31;
    const float* g = g2 + (size_t)row * H2;
    float4 gv = *reinterpret_cast<const float4*>(&g[lane * 4]);
    float4 wv = *reinterpret_cast<const float4*>(&Wg[lane * 4]);
    float s = gv.x * wv.x + gv.y * wv.y + gv.z * wv.z + gv.w * wv.w;
    #pragma unroll
    for (int o = 16; o; o >>= 1) s += __shfl_xor_sync(0xffffffffu, s, o);
    if (lane == 0) v[row] = s;
}

// ---------------- out[b,i] = leaky( fc2[b,i,:] . v[b,:] + bg ) --------------
__global__ __launch_bounds__(256) void z_kernel(
    const float* __restrict__ fc2, const float* __restrict__ v,
    const float* __restrict__ bg, float* __restrict__ out)
{
    __shared__ float vs[NN];
    int b = blockIdx.x >> 7;                       // 128 blocks per batch
    int rloc = (blockIdx.x & 127) * 8 + (threadIdx.x >> 5);
    int lane = threadIdx.x & 31;
    *reinterpret_cast<float4*>(&vs[threadIdx.x * 4]) =
        *reinterpret_cast<const float4*>(&v[b * NN + threadIdx.x * 4]);
    __syncthreads();
    size_t row = (size_t)b * NN + rloc;
    const float* f = fc2 + row * NN;
    float s = 0.f;
    for (int j = lane * 4; j < NN; j += 128) {
        float4 a = *reinterpret_cast<const float4*>(f + j);
        s += a.x * vs[j] + a.y * vs[j + 1] + a.z * vs[j + 2] + a.w * vs[j + 3];
    }
    #pragma unroll
    for (int o = 16; o; o >>= 1) s += __shfl_xor_sync(0xffffffffu, s, o);
    if (lane == 0) {
        float zz = s + bg[0];
        out[row] = zz > 0.f ? zz : 0.01f * zz;
    }
}

// ---------------- launch ----------------------------------------------------
extern "C" void kernel_launch(void* const* d_in, const int* in_sizes, int n_in,
                              void* d_out, int out_size)
{
    const float* x  = (const float*)d_in[0];
    // d_in[1] = edge_weight (unused by the reference)
    const float* W1 = (const float*)d_in[2];
    const float* a1 = (const float*)d_in[3];
    const float* W2 = (const float*)d_in[4];
    const float* a2 = (const float*)d_in[5];
    const float* Wg = (const float*)d_in[6];
    const float* bg = (const float*)d_in[7];

    float* out = (float*)d_out;                                 // [B,N,1]
    float* fc2 = out + (size_t)BB * NN;                         // [B,N,N]
    float* g2  = fc2 + (size_t)BB * NN * NN;                    // [B,N,H2]

    float *h1, *g1, *h2, *el1, *er1, *el2, *er2, *st1, *st2, *vv;
    cudaGetSymbolAddress((void**)&h1,  g_h1);
    cudaGetSymbolAddress((void**)&g1,  g_g1);
    cudaGetSymbolAddress((void**)&h2,  g_h2);
    cudaGetSymbolAddress((void**)&el1, g_el1);
    cudaGetSymbolAddress((void**)&er1, g_er1);
    cudaGetSymbolAddress((void**)&el2, g_el2);
    cudaGetSymbolAddress((void**)&er2, g_er2);
    cudaGetSymbolAddress((void**)&st1, g_st1);
    cudaGetSymbolAddress((void**)&st2, g_st2);
    cudaGetSymbolAddress((void**)&vv,  g_v);

    // Layer 1
    gemm_kernel<FIN, H1><<<dim3(BB * NN / 64, H1 / 64), 256>>>(x, W1, h1);
    eler_kernel<H1><<<BB * NN / 8, 256>>>(h1, a1, el1, er1);
    stat_kernel<<<BB, 256>>>(el1, er1, st1);
    attn_kernel<H1, false, true><<<dim3(NN / 64, H1 / 128, BB), 256>>>(
        el1, er1, st1, h1, g1, nullptr);

    // Layer 2
    gemm_kernel<H1, H2><<<dim3(BB * NN / 64, H2 / 64), 256>>>(g1, W2, h2);
    eler_kernel<H2><<<BB * NN / 8, 256>>>(h2, a2, el2, er2);
    stat_kernel<<<BB, 256>>>(el2, er2, st2);
    attn_kernel<H2, true, false><<<dim3(NN / 64, H2 / 128, BB), 256>>>(
        el2, er2, st2, h2, g2, fc2);

    // Readout: z = fc2 @ (g2 @ Wg) + bg ; out = leaky(z)
    v_kernel<<<BB * NN / 8, 256>>>(g2, Wg, vv);
    z_kernel<<<BB * NN / 8, 256>>>(fc2, vv, bg, out);
}

// round 6
// speedup vs baseline: 1.0030x; 1.0012x over previous
#include <cuda_runtime.h>
#include <cuda_bf16.h>
#include <cstdint>

// Problem constants
#define BB 32
#define NN 1024
#define FIN 512
#define H1 256
#define H2 128

// ---------------- scratch (static device globals; no allocations allowed) ---
__device__ float g_h1[(size_t)BB * NN * H1];   // 33.5 MB
__device__ float g_g1[(size_t)BB * NN * H1];   // 33.5 MB
__device__ float g_h2[(size_t)BB * NN * H2];   // 16.8 MB
__device__ float g_el1[BB * NN], g_er1[BB * NN];
__device__ float g_el2[BB * NN], g_er2[BB * NN];
__device__ float g_st1[2 * BB], g_st2[2 * BB];
__device__ float g_v[BB * NN];

// ---------------- generic tiled GEMM: C[M,NC] = A[M,K] @ W[K,NC] ------------
// BM=64, BN=64, BK=16, 256 threads, 4x4 per-thread tile.
template<int K, int NC>
__global__ __launch_bounds__(256) void gemm_kernel(
    const float* __restrict__ A, const float* __restrict__ W, float* __restrict__ C)
{
    __shared__ float As[16][65];   // [k][m], padded
    __shared__ float Bs[16][64];   // [k][n]
    const int tid = threadIdx.x;
    const int m0 = blockIdx.x * 64, n0 = blockIdx.y * 64;
    const int ty = tid >> 4, tx = tid & 15;
    const int arow = tid >> 2, acol = (tid & 3) * 4;
    const int brow = tid >> 4, bcol = (tid & 15) * 4;
    const float* Ap = A + (size_t)(m0 + arow) * K + acol;

    float acc[4][4] = {};
    for (int k0 = 0; k0 < K; k0 += 16) {
        float4 av = *reinterpret_cast<const float4*>(Ap + k0);
        As[acol + 0][arow] = av.x; As[acol + 1][arow] = av.y;
        As[acol + 2][arow] = av.z; As[acol + 3][arow] = av.w;
        float4 wv = *reinterpret_cast<const float4*>(
            W + (size_t)(k0 + brow) * NC + n0 + bcol);
        *reinterpret_cast<float4*>(&Bs[brow][bcol]) = wv;
        __syncthreads();
        #pragma unroll
        for (int k = 0; k < 16; k++) {
            float a[4];
            #pragma unroll
            for (int i = 0; i < 4; i++) a[i] = As[k][ty * 4 + i];
            float4 bv = *reinterpret_cast<const float4*>(&Bs[k][tx * 4]);
            float bb[4] = {bv.x, bv.y, bv.z, bv.w};
            #pragma unroll
            for (int i = 0; i < 4; i++)
                #pragma unroll
                for (int j = 0; j < 4; j++)
                    acc[i][j] = fmaf(a[i], bb[j], acc[i][j]);
        }
        __syncthreads();
    }
    #pragma unroll
    for (int i = 0; i < 4; i++) {
        float4 o = {acc[i][0], acc[i][1], acc[i][2], acc[i][3]};
        *reinterpret_cast<float4*>(&C[(size_t)(m0 + ty * 4 + i) * NC + n0 + tx * 4]) = o;
    }
}

// ---------------- el/er projections: el[r] = h[r,:].a[0:FO], er uses a[FO:] -
template<int FO>
__global__ __launch_bounds__(256) void eler_kernel(
    const float* __restrict__ H, const float* __restrict__ a,
    float* __restrict__ el, float* __restrict__ er)
{
    int row = (blockIdx.x * 256 + threadIdx.x) >> 5;
    int lane = threadIdx.x & 31;
    const float* h = H + (size_t)row * FO;
    float se = 0.f, sr = 0.f;
    #pragma unroll
    for (int f = lane * 4; f < FO; f += 128) {
        float4 hv = *reinterpret_cast<const float4*>(h + f);
        float4 al = *reinterpret_cast<const float4*>(a + f);
        float4 ar = *reinterpret_cast<const float4*>(a + FO + f);
        se += hv.x * al.x + hv.y * al.y + hv.z * al.z + hv.w * al.w;
        sr += hv.x * ar.x + hv.y * ar.y + hv.z * ar.z + hv.w * ar.w;
    }
    #pragma unroll
    for (int o = 16; o; o >>= 1) {
        se += __shfl_xor_sync(0xffffffffu, se, o);
        sr += __shfl_xor_sync(0xffffffffu, sr, o);
    }
    if (lane == 0) { el[row] = se; er[row] = sr; }
}

// ---------------- per-batch min/max -> affine coefficients ------------------
// att(i,j) = sigmoid(leaky(el_i+er_j)*c1 + c0); c1=30/(mx-mn), c0=-mn*c1-20
__global__ __launch_bounds__(256) void stat_kernel(
    const float* __restrict__ el, const float* __restrict__ er, float* __restrict__ st)
{
    int b = blockIdx.x, tid = threadIdx.x;
    const float* e1 = el + b * NN;
    const float* e2 = er + b * NN;
    float mnl = 1e30f, mxl = -1e30f, mnr = 1e30f, mxr = -1e30f;
    for (int i = tid; i < NN; i += 256) {
        float v = e1[i]; mnl = fminf(mnl, v); mxl = fmaxf(mxl, v);
        float w = e2[i]; mnr = fminf(mnr, w); mxr = fmaxf(mxr, w);
    }
    #pragma unroll
    for (int o = 16; o; o >>= 1) {
        mnl = fminf(mnl, __shfl_xor_sync(0xffffffffu, mnl, o));
        mxl = fmaxf(mxl, __shfl_xor_sync(0xffffffffu, mxl, o));
        mnr = fminf(mnr, __shfl_xor_sync(0xffffffffu, mnr, o));
        mxr = fmaxf(mxr, __shfl_xor_sync(0xffffffffu, mxr, o));
    }
    __shared__ float sm[4][8];
    int wid = tid >> 5, lane = tid & 31;
    if (lane == 0) { sm[0][wid] = mnl; sm[1][wid] = mxl; sm[2][wid] = mnr; sm[3][wid] = mxr; }
    __syncthreads();
    if (tid == 0) {
        for (int w = 1; w < 8; w++) {
            mnl = fminf(mnl, sm[0][w]); mxl = fmaxf(mxl, sm[1][w]);
            mnr = fminf(mnr, sm[2][w]); mxr = fmaxf(mxr, sm[3][w]);
        }
        float s = mnl + mnr, t = mxl + mxr;
        float mn = s > 0.f ? s : 0.01f * s;
        float mx = t > 0.f ? t : 0.01f * t;
        float c1 = 30.f / (mx - mn);
        st[2 * b] = c1;
        st[2 * b + 1] = -mn * c1 - 20.f;
    }
}

// ---------------- attention GEMM: G = [ELU]( att @ H ), att on-the-fly ------
// Per batch (grid.z). BM=64 rows, BN=128 cols, BK=32. 256 threads, 4x8 tile.
// Optionally writes the att tile to attOut (layer 2: fc2 is an output).
template<int FOUT, bool WRITE_ATT, bool DO_ELU>
__global__ __launch_bounds__(256) void attn_kernel(
    const float* __restrict__ el, const float* __restrict__ er,
    const float* __restrict__ st, const float* __restrict__ H,
    float* __restrict__ G, float* __restrict__ attOut)
{
    __shared__ float As[32][65];    // [k][m] att tile, padded
    __shared__ float Bs[32][128];   // [k][n] H tile
    const int b = blockIdx.z;
    const int i0 = blockIdx.x * 64;
    const int n0 = blockIdx.y * 128;
    const int tid = threadIdx.x;
    const int ty = tid >> 4, tx = tid & 15;
    const int am = tid >> 2, ak = (tid & 3) * 8;
    const float c1 = st[2 * b], c0 = st[2 * b + 1];
    const float* erb = er + b * NN;
    const float el_m = el[b * NN + i0 + am];
    const float* Hb = H + (size_t)b * NN * FOUT;
    const int lr = tid >> 5, lc = (tid & 31) * 4;

    float acc[4][8] = {};
    for (int k0 = 0; k0 < NN; k0 += 32) {
        // stage H tile
        #pragma unroll
        for (int it = 0; it < 4; it++) {
            int r = lr + it * 8;
            *reinterpret_cast<float4*>(&Bs[r][lc]) =
                *reinterpret_cast<const float4*>(&Hb[(size_t)(k0 + r) * FOUT + n0 + lc]);
        }
        // compute att tile (8 values per thread)
        float attv[8];
        #pragma unroll
        for (int q = 0; q < 8; q++) {
            float s = el_m + erb[k0 + ak + q];
            float l = s > 0.f ? s : 0.01f * s;
            float t = fmaf(l, c1, c0);
            float a = 1.f / (1.f + __expf(-t));
            attv[q] = a;
            As[ak + q][am] = a;
        }
        if constexpr (WRITE_ATT) {
            size_t base = ((size_t)b * NN + i0 + am) * NN + k0 + ak;
            float4 p0 = {attv[0], attv[1], attv[2], attv[3]};
            float4 p1 = {attv[4], attv[5], attv[6], attv[7]};
            *reinterpret_cast<float4*>(&attOut[base]) = p0;
            *reinterpret_cast<float4*>(&attOut[base + 4]) = p1;
        }
        __syncthreads();
        #pragma unroll
        for (int k = 0; k < 32; k++) {
            float a[4];
            #pragma unroll
            for (int i = 0; i < 4; i++) a[i] = As[k][ty * 4 + i];
            float4 b0 = *reinterpret_cast<const float4*>(&Bs[k][tx * 8]);
            float4 b1 = *reinterpret_cast<const float4*>(&Bs[k][tx * 8 + 4]);
            float bb[8] = {b0.x, b0.y, b0.z, b0.w, b1.x, b1.y, b1.z, b1.w};
            #pragma unroll
            for (int i = 0; i < 4; i++)
                #pragma unroll
                for (int j = 0; j < 8; j++)
                    acc[i][j] = fmaf(a[i], bb[j], acc[i][j]);
        }
        __syncthreads();
    }
    #pragma unroll
    for (int i = 0; i < 4; i++) {
        float o[8];
        #pragma unroll
        for (int j = 0; j < 8; j++) {
            float v = acc[i][j];
            if constexpr (DO_ELU) v = v > 0.f ? v : (__expf(v) - 1.f);
            o[j] = v;
        }
        float* dst = &G[(size_t)(b * NN + i0 + ty * 4 + i) * FOUT + n0 + tx * 8];
        float4 q0 = {o[0], o[1], o[2], o[3]}, q1 = {o[4], o[5], o[6], o[7]};
        *reinterpret_cast<float4*>(dst) = q0;
        *reinterpret_cast<float4*>(dst + 4) = q1;
    }
}

// ---------------- v[r] = g2[r,:] . Wg  (H2=128) -----------------------------
__global__ __launch_bounds__(256) void v_kernel(
    const float* __restrict__ g2, const float* __restrict__ Wg, float* __restrict__ v)
{
    int row = (blockIdx.x * 256 + threadIdx.x) >> 5;
    int lane = threadIdx.x & 31;
    const float* g = g2 + (size_t)row * H2;
    float4 gv = *reinterpret_cast<const float4*>(&g[lane * 4]);
    float4 wv = *reinterpret_cast<const float4*>(&Wg[lane * 4]);
    float s = gv.x * wv.x + gv.y * wv.y + gv.z * wv.z + gv.w * wv.w;
    #pragma unroll
    for (int o = 16; o; o >>= 1) s += __shfl_xor_sync(0xffffffffu, s, o);
    if (lane == 0) v[row] = s;
}

// ---------------- out[b,i] = leaky( fc2[b,i,:] . v[b,:] + bg ) --------------
__global__ __launch_bounds__(256) void z_kernel(
    const float* __restrict__ fc2, const float* __restrict__ v,
    const float* __restrict__ bg, float* __restrict__ out)
{
    __shared__ float vs[NN];
    int b = blockIdx.x >> 7;                       // 128 blocks per batch
    int rloc = (blockIdx.x & 127) * 8 + (threadIdx.x >> 5);
    int lane = threadIdx.x & 31;
    *reinterpret_cast<float4*>(&vs[threadIdx.x * 4]) =
        *reinterpret_cast<const float4*>(&v[b * NN + threadIdx.x * 4]);
    __syncthreads();
    size_t row = (size_t)b * NN + rloc;
    const float* f = fc2 + row * NN;
    float s = 0.f;
    for (int j = lane * 4; j < NN; j += 128) {
        float4 a = *reinterpret_cast<const float4*>(f + j);
        s += a.x * vs[j] + a.y * vs[j + 1] + a.z * vs[j + 2] + a.w * vs[j + 3];
    }
    #pragma unroll
    for (int o = 16; o; o >>= 1) s += __shfl_xor_sync(0xffffffffu, s, o);
    if (lane == 0) {
        float zz = s + bg[0];
        out[row] = zz > 0.f ? zz : 0.01f * zz;
    }
}

// ---------------- launch ----------------------------------------------------
extern "C" void kernel_launch(void* const* d_in, const int* in_sizes, int n_in,
                              void* d_out, int out_size)
{
    const float* x  = (const float*)d_in[0];
    // d_in[1] = edge_weight (unused by the reference)
    const float* W1 = (const float*)d_in[2];
    const float* a1 = (const float*)d_in[3];
    const float* W2 = (const float*)d_in[4];
    const float* a2 = (const float*)d_in[5];
    const float* Wg = (const float*)d_in[6];
    const float* bg = (const float*)d_in[7];

    float* out = (float*)d_out;                                 // [B,N,1]
    float* fc2 = out + (size_t)BB * NN;                         // [B,N,N]
    float* g2  = fc2 + (size_t)BB * NN * NN;                    // [B,N,H2]

    float *h1, *g1, *h2, *el1, *er1, *el2, *er2, *st1, *st2, *vv;
    cudaGetSymbolAddress((void**)&h1,  g_h1);
    cudaGetSymbolAddress((void**)&g1,  g_g1);
    cudaGetSymbolAddress((void**)&h2,  g_h2);
    cudaGetSymbolAddress((void**)&el1, g_el1);
    cudaGetSymbolAddress((void**)&er1, g_er1);
    cudaGetSymbolAddress((void**)&el2, g_el2);
    cudaGetSymbolAddress((void**)&er2, g_er2);
    cudaGetSymbolAddress((void**)&st1, g_st1);
    cudaGetSymbolAddress((void**)&st2, g_st2);
    cudaGetSymbolAddress((void**)&vv,  g_v);

    // Layer 1
    gemm_kernel<FIN, H1><<<dim3(BB * NN / 64, H1 / 64), 256>>>(x, W1, h1);
    eler_kernel<H1><<<BB * NN / 8, 256>>>(h1, a1, el1, er1);
    stat_kernel<<<BB, 256>>>(el1, er1, st1);
    attn_kernel<H1, false, true><<<dim3(NN / 64, H1 / 128, BB), 256>>>(
        el1, er1, st1, h1, g1, nullptr);

    // Layer 2
    gemm_kernel<H1, H2><<<dim3(BB * NN / 64, H2 / 64), 256>>>(g1, W2, h2);
    eler_kernel<H2><<<BB * NN / 8, 256>>>(h2, a2, el2, er2);
    stat_kernel<<<BB, 256>>>(el2, er2, st2);
    attn_kernel<H2, true, false><<<dim3(NN / 64, H2 / 128, BB), 256>>>(
        el2, er2, st2, h2, g2, fc2);

    // Readout: z = fc2 @ (g2 @ Wg) + bg ; out = leaky(z)
    v_kernel<<<BB * NN / 8, 256>>>(g2, Wg, vv);
    z_kernel<<<BB * NN / 8, 256>>>(fc2, vv, bg, out);
}